// round 5
// baseline (speedup 1.0000x reference)
#include <cuda_runtime.h>

#define BATCH 4
#define CIN   256
#define DIM   64
#define HWDIM 64
#define NPIX  4096
#define LN_EPS 1e-5f

// ---------------- scratch (device globals; no allocation allowed) ----------
__device__ float g_att[BATCH * DIM * NPIX];   // inner projection out [b][d][n]
__device__ float g_q  [BATCH * DIM * NPIX];   // [b][d][n]
__device__ float g_k  [BATCH * DIM * NPIX];   // [b][d][n]
__device__ float g_vt [BATCH * NPIX * DIM];   // V transposed: [b][n][d]
__device__ float g_ao [BATCH * DIM * NPIX];   // attention out [b][d][n]

// ============================================================================
// Kernel 1: 1x1 in-projection  att[b,d,n] = sum_c w_in[d,c] * x[b,c,n] + b_in
// Tiled GEMM: M=64 (d), Npix tile=64, K=256. 256 threads, 4x4 microtile.
// ============================================================================
__global__ __launch_bounds__(256) void k_proj_in(
    const float* __restrict__ x, const float* __restrict__ w,
    const float* __restrict__ bias)
{
    __shared__ float ws[32 * 68];   // [ci][d], stride 68 (16B aligned, few conflicts)
    __shared__ float xs[32 * 68];   // [ci][p]
    const int b   = blockIdx.y;
    const int n0  = blockIdx.x * 64;
    const int tid = threadIdx.x;
    const int ti  = tid >> 4;       // d group 0..15
    const int tj  = tid & 15;       // pixel group 0..15

    float acc[4][4] = {};

    for (int c0 = 0; c0 < CIN; c0 += 32) {
        __syncthreads();
        #pragma unroll
        for (int t = 0; t < 8; t++) {                 // 2048 weight elems
            int idx = tid + t * 256;
            int d = idx >> 5, ci = idx & 31;
            ws[ci * 68 + d] = w[d * CIN + c0 + ci];   // coalesced read, transpose store
        }
        #pragma unroll
        for (int t = 0; t < 2; t++) {                 // 512 float4 of x
            int idx4 = tid + t * 256;
            int ci = idx4 >> 4, p4 = idx4 & 15;
            float4 v = *(const float4*)&x[((b * CIN) + c0 + ci) * NPIX + n0 + p4 * 4];
            *(float4*)&xs[ci * 68 + p4 * 4] = v;
        }
        __syncthreads();
        #pragma unroll
        for (int ci = 0; ci < 32; ci++) {
            float4 a4 = *(const float4*)&ws[ci * 68 + 4 * ti];
            float4 b4 = *(const float4*)&xs[ci * 68 + 4 * tj];
            acc[0][0] += a4.x * b4.x; acc[0][1] += a4.x * b4.y;
            acc[0][2] += a4.x * b4.z; acc[0][3] += a4.x * b4.w;
            acc[1][0] += a4.y * b4.x; acc[1][1] += a4.y * b4.y;
            acc[1][2] += a4.y * b4.z; acc[1][3] += a4.y * b4.w;
            acc[2][0] += a4.z * b4.x; acc[2][1] += a4.z * b4.y;
            acc[2][2] += a4.z * b4.z; acc[2][3] += a4.z * b4.w;
            acc[3][0] += a4.w * b4.x; acc[3][1] += a4.w * b4.y;
            acc[3][2] += a4.w * b4.z; acc[3][3] += a4.w * b4.w;
        }
    }
    #pragma unroll
    for (int di = 0; di < 4; di++) {
        int d = 4 * ti + di;
        float bb = bias[d];
        float4 o = make_float4(acc[di][0] + bb, acc[di][1] + bb,
                               acc[di][2] + bb, acc[di][3] + bb);
        *(float4*)&g_att[((b * DIM) + d) * NPIX + n0 + 4 * tj] = o;
    }
}

// ============================================================================
// Kernel 2: 3x3 conv (pad 1). blockIdx.z selects q/k/v. 8x8 spatial tile,
// all 64 output channels. threads = 64 d x 4 subtiles(4x4).
// V is stored TRANSPOSED ([b][n][d]) so the flash kernel's P*V GEMM reads
// conflict-free float4 rows without smem padding.
// ============================================================================
__global__ __launch_bounds__(256) void k_qkv(
    const float* __restrict__ wq, const float* __restrict__ bq,
    const float* __restrict__ wk, const float* __restrict__ bk,
    const float* __restrict__ wv, const float* __restrict__ bv)
{
    __shared__ float att_s[DIM * 100];   // [c][10][10] halo tile
    __shared__ float ws[8 * 64 * 9];     // weight chunk: [ci][d][k]

    const int b = blockIdx.y;
    const int z = blockIdx.z;
    const float* w    = (z == 0) ? wq : (z == 1) ? wk : wv;
    const float* bias = (z == 0) ? bq : (z == 1) ? bk : bv;

    const int tile = blockIdx.x;
    const int th = (tile >> 3) * 8, tw = (tile & 7) * 8;
    const int tid = threadIdx.x;

    // load 10x10 halo tile for all 64 channels (zero padded)
    for (int idx = tid; idx < DIM * 100; idx += 256) {
        int c = idx / 100, rem = idx - c * 100;
        int r = rem / 10, cc = rem - r * 10;
        int gh = th - 1 + r, gw = tw - 1 + cc;
        float v = 0.f;
        if (gh >= 0 && gh < HWDIM && gw >= 0 && gw < HWDIM)
            v = g_att[((b * DIM) + c) * NPIX + gh * HWDIM + gw];
        att_s[idx] = v;
    }

    const int d  = tid & 63;
    const int sub = tid >> 6;
    const int sy = (sub >> 1) * 4, sx = (sub & 1) * 4;
    float acc[16] = {};

    for (int c8 = 0; c8 < 8; c8++) {
        __syncthreads();  // protects previous ws use (and covers att_s load at c8=0)
        #pragma unroll
        for (int t = 0; t < 18; t++) {               // 4608 weight elems
            int idx = tid + t * 256;
            int ci = idx / 576, rem2 = idx - ci * 576;
            int dd = rem2 / 9, k = rem2 - dd * 9;
            ws[idx] = w[(dd * DIM + c8 * 8 + ci) * 9 + k];
        }
        __syncthreads();
        #pragma unroll
        for (int ci = 0; ci < 8; ci++) {
            int c = c8 * 8 + ci;
            float patch[36];
            #pragma unroll
            for (int ry = 0; ry < 6; ry++)
                #pragma unroll
                for (int rx = 0; rx < 6; rx++)
                    patch[ry * 6 + rx] = att_s[c * 100 + (sy + ry) * 10 + sx + rx];
            const float* wp = &ws[(ci * 64 + d) * 9];
            float w9[9];
            #pragma unroll
            for (int k = 0; k < 9; k++) w9[k] = wp[k];
            #pragma unroll
            for (int py = 0; py < 4; py++)
                #pragma unroll
                for (int px = 0; px < 4; px++) {
                    float a = acc[py * 4 + px];
                    #pragma unroll
                    for (int ky = 0; ky < 3; ky++)
                        #pragma unroll
                        for (int kx = 0; kx < 3; kx++)
                            a += w9[ky * 3 + kx] * patch[(py + ky) * 6 + px + kx];
                    acc[py * 4 + px] = a;
                }
        }
    }

    float bb = bias[d];
    if (z == 2) {
        #pragma unroll
        for (int py = 0; py < 4; py++)
            #pragma unroll
            for (int px = 0; px < 4; px++) {
                int n = (th + sy + py) * HWDIM + tw + sx + px;
                g_vt[(b * NPIX + n) * DIM + d] = acc[py * 4 + px] + bb;
            }
    } else {
        float* out = (z == 0) ? g_q : g_k;
        #pragma unroll
        for (int py = 0; py < 4; py++)
            #pragma unroll
            for (int px = 0; px < 4; px++) {
                int n = (th + sy + py) * HWDIM + tw + sx + px;
                out[((b * DIM) + d) * NPIX + n] = acc[py * 4 + px] + bb;
            }
    }
}

// ============================================================================
// Kernel 3: flash attention, fp32. BM=BN=64, head dim 64, no 1/sqrt(d) scale.
// energy[i,j] = sum_c q[c,i] k[c,j]; softmax over j; o[c,i] = sum_j p[i,j] v[c,j]
// smem: Qs[64x64] + KPs[64x64] (K tile, reused as P tile) + Vt[64x64] = 48KB.
// 256 threads = 16 (ti: query groups) x 16 (tj: key / channel groups), 4x4 micro.
// ============================================================================
__global__ __launch_bounds__(256) void k_flash()
{
    __shared__ float Qs [64 * 64];   // [c][i]
    __shared__ float KPs[64 * 64];   // phase A: K [c][j]; phase B: P [i][j]
    __shared__ float Vt [64 * 64];   // [j][c]

    const int b  = blockIdx.y;
    const int i0 = blockIdx.x * 64;
    const int tid = threadIdx.x;
    const int ti = tid >> 4;   // 0..15 query group
    const int tj = tid & 15;   // 0..15 key group / channel group

    #pragma unroll
    for (int t = 0; t < 4; t++) {
        int idx4 = tid + t * 256;
        int c = idx4 >> 4, p4 = idx4 & 15;
        *(float4*)&Qs[c * 64 + p4 * 4] =
            *(const float4*)&g_q[((b * DIM) + c) * NPIX + i0 + p4 * 4];
    }

    float o[4][4] = {};
    float m[4], l[4];
    #pragma unroll
    for (int ii = 0; ii < 4; ii++) { m[ii] = -1e30f; l[ii] = 0.f; }

    for (int jt = 0; jt < 64; jt++) {
        const int j0 = jt * 64;
        __syncthreads();   // previous GEMM2 reads of KPs/Vt done
        #pragma unroll
        for (int t = 0; t < 4; t++) {
            int idx4 = tid + t * 256;
            int r = idx4 >> 4, q4 = idx4 & 15;
            *(float4*)&KPs[r * 64 + q4 * 4] =
                *(const float4*)&g_k[((b * DIM) + r) * NPIX + j0 + q4 * 4];
            *(float4*)&Vt[r * 64 + q4 * 4] =
                *(const float4*)&g_vt[(b * NPIX + j0 + r) * DIM + q4 * 4];
        }
        __syncthreads();

        // S = Q^T K  (4x4 microtile per thread)
        float s[4][4] = {};
        #pragma unroll 8
        for (int c = 0; c < 64; c++) {
            float4 a4 = *(const float4*)&Qs [c * 64 + 4 * ti];
            float4 b4 = *(const float4*)&KPs[c * 64 + 4 * tj];
            s[0][0] += a4.x * b4.x; s[0][1] += a4.x * b4.y;
            s[0][2] += a4.x * b4.z; s[0][3] += a4.x * b4.w;
            s[1][0] += a4.y * b4.x; s[1][1] += a4.y * b4.y;
            s[1][2] += a4.y * b4.z; s[1][3] += a4.y * b4.w;
            s[2][0] += a4.z * b4.x; s[2][1] += a4.z * b4.y;
            s[2][2] += a4.z * b4.z; s[2][3] += a4.z * b4.w;
            s[3][0] += a4.w * b4.x; s[3][1] += a4.w * b4.y;
            s[3][2] += a4.w * b4.z; s[3][3] += a4.w * b4.w;
        }

        // online softmax (row stats shared by the 16 tj lanes of each ti group)
        float p[4][4], sc[4];
        #pragma unroll
        for (int ii = 0; ii < 4; ii++) {
            float mt = fmaxf(fmaxf(s[ii][0], s[ii][1]), fmaxf(s[ii][2], s[ii][3]));
            mt = fmaxf(mt, __shfl_xor_sync(0xffffffffu, mt, 8, 16));
            mt = fmaxf(mt, __shfl_xor_sync(0xffffffffu, mt, 4, 16));
            mt = fmaxf(mt, __shfl_xor_sync(0xffffffffu, mt, 2, 16));
            mt = fmaxf(mt, __shfl_xor_sync(0xffffffffu, mt, 1, 16));
            float mn = fmaxf(m[ii], mt);
            sc[ii] = __expf(m[ii] - mn);
            float rs = 0.f;
            #pragma unroll
            for (int jj = 0; jj < 4; jj++) {
                p[ii][jj] = __expf(s[ii][jj] - mn);
                rs += p[ii][jj];
            }
            rs += __shfl_xor_sync(0xffffffffu, rs, 8, 16);
            rs += __shfl_xor_sync(0xffffffffu, rs, 4, 16);
            rs += __shfl_xor_sync(0xffffffffu, rs, 2, 16);
            rs += __shfl_xor_sync(0xffffffffu, rs, 1, 16);
            l[ii] = l[ii] * sc[ii] + rs;
            m[ii] = mn;
        }

        __syncthreads();   // all GEMM1 reads of K done before P overwrites buffer
        #pragma unroll
        for (int ii = 0; ii < 4; ii++)
            *(float4*)&KPs[(4 * ti + ii) * 64 + 4 * tj] =
                make_float4(p[ii][0], p[ii][1], p[ii][2], p[ii][3]);
        #pragma unroll
        for (int ii = 0; ii < 4; ii++)
            #pragma unroll
            for (int cc = 0; cc < 4; cc++) o[ii][cc] *= sc[ii];
        __syncthreads();   // P visible

        // O += P * V   (o[ii][cc]: query 4ti+ii, channel 4tj+cc)
        #pragma unroll 8
        for (int j = 0; j < 64; j++) {
            float4 v4 = *(const float4*)&Vt[j * 64 + 4 * tj];
            #pragma unroll
            for (int ii = 0; ii < 4; ii++) {
                float pv = KPs[(4 * ti + ii) * 64 + j];
                o[ii][0] += pv * v4.x; o[ii][1] += pv * v4.y;
                o[ii][2] += pv * v4.z; o[ii][3] += pv * v4.w;
            }
        }
    }

    #pragma unroll
    for (int ii = 0; ii < 4; ii++) {
        float inv = 1.f / l[ii];
        #pragma unroll
        for (int cc = 0; cc < 4; cc++)
            g_ao[((b * DIM) + 4 * tj + cc) * NPIX + i0 + 4 * ti + ii] =
                o[ii][cc] * inv;
    }
}

// ============================================================================
// Kernel 4: out = LayerNorm_c( gamma*x + (w_out @ ao + b_out) )
// block = 16 pixels, 256 threads (one per output channel).
// ============================================================================
__global__ __launch_bounds__(256) void k_out_ln(
    const float* __restrict__ x, const float* __restrict__ w_out,
    const float* __restrict__ b_out, const float* __restrict__ gamma,
    const float* __restrict__ ln_w, const float* __restrict__ ln_b,
    float* __restrict__ out)
{
    __shared__ float aos[DIM * 16];    // [d][p]
    __shared__ float red1[8 * 16];
    __shared__ float red2[8 * 16];
    __shared__ float mus[16], rstds[16];

    const int blk = blockIdx.x;
    const int b  = blk >> 8;            // 256 blocks per batch
    const int n0 = (blk & 255) * 16;
    const int c  = threadIdx.x;

    #pragma unroll
    for (int t = 0; t < 4; t++) {
        int idx = c + t * 256;
        int d = idx >> 4, p = idx & 15;
        aos[idx] = g_ao[((b * DIM) + d) * NPIX + n0 + p];
    }
    float wreg[64];
    #pragma unroll
    for (int t = 0; t < 16; t++)
        *(float4*)&wreg[t * 4] = *(const float4*)&w_out[c * DIM + t * 4];
    const float g0 = gamma[0];
    const float bo = b_out[c];
    __syncthreads();

    float tv[16];
    #pragma unroll
    for (int p = 0; p < 16; p++) {
        float acc = bo;
        #pragma unroll
        for (int d = 0; d < 64; d++) acc += wreg[d] * aos[d * 16 + p];
        tv[p] = g0 * x[((b * CIN) + c) * NPIX + n0 + p] + acc;
    }

    const int warp = c >> 5, lane = c & 31;
    #pragma unroll
    for (int p = 0; p < 16; p++) {
        float s1 = tv[p], s2 = tv[p] * tv[p];
        #pragma unroll
        for (int off = 16; off > 0; off >>= 1) {
            s1 += __shfl_xor_sync(0xffffffffu, s1, off);
            s2 += __shfl_xor_sync(0xffffffffu, s2, off);
        }
        if (lane == 0) { red1[warp * 16 + p] = s1; red2[warp * 16 + p] = s2; }
    }
    __syncthreads();
    if (c < 16) {
        float s1 = 0.f, s2 = 0.f;
        #pragma unroll
        for (int w = 0; w < 8; w++) { s1 += red1[w * 16 + c]; s2 += red2[w * 16 + c]; }
        float mu  = s1 * (1.f / 256.f);
        float var = s2 * (1.f / 256.f) - mu * mu;
        mus[c] = mu;
        rstds[c] = rsqrtf(var + LN_EPS);
    }
    __syncthreads();

    const float lw = ln_w[c], lb = ln_b[c];
    #pragma unroll
    for (int p = 0; p < 16; p++)
        out[((b * CIN) + c) * NPIX + n0 + p] =
            (tv[p] - mus[p]) * rstds[p] * lw + lb;
}

// ============================================================================
extern "C" void kernel_launch(void* const* d_in, const int* in_sizes, int n_in,
                              void* d_out, int out_size)
{
    const float* x     = (const float*)d_in[0];
    const float* w_in  = (const float*)d_in[1];
    const float* b_in  = (const float*)d_in[2];
    const float* wq    = (const float*)d_in[3];
    const float* bq    = (const float*)d_in[4];
    const float* wk    = (const float*)d_in[5];
    const float* bk    = (const float*)d_in[6];
    const float* wv    = (const float*)d_in[7];
    const float* bv    = (const float*)d_in[8];
    const float* w_out = (const float*)d_in[9];
    const float* b_out = (const float*)d_in[10];
    const float* gamma = (const float*)d_in[11];
    const float* ln_w  = (const float*)d_in[12];
    const float* ln_b  = (const float*)d_in[13];
    float* out = (float*)d_out;

    k_proj_in<<<dim3(64, BATCH), 256>>>(x, w_in, b_in);
    k_qkv<<<dim3(64, BATCH, 3), 256>>>(wq, bq, wk, bk, wv, bv);
    k_flash<<<dim3(64, BATCH), 256>>>();
    k_out_ln<<<BATCH * 256, 256>>>(x, w_out, b_out, gamma, ln_w, ln_b, out);
}